// round 1
// baseline (speedup 1.0000x reference)
#include <cuda_runtime.h>
#include <cuda_bf16.h>

// Problem constants
#define BATCH  2048
#define NITEMS 20000
#define EMB    512
#define HID    1024   // 2*D

// ---------------------------------------------------------------------------
// Scratch (no allocations allowed -> __device__ globals)
// ---------------------------------------------------------------------------
__device__ float g_H[(size_t)BATCH * HID];     // hidden activations (reused by both heads)
__device__ float g_E[(size_t)BATCH * EMB];     // embed_user
__device__ float g_Nrm[(size_t)BATCH * EMB];   // l2-normalized embed
__device__ float g_part[16 * NITEMS];          // popular partial sums
__device__ int   g_mask_mode;                  // 0=u8, 1=i32, 2=f32

// ---------------------------------------------------------------------------
// Packed f32x2 helpers (Blackwell FFMA2 path, PTX-only)
// ---------------------------------------------------------------------------
__device__ __forceinline__ unsigned long long pack2(float x, float y) {
    unsigned long long r;
    asm("mov.b64 %0, {%1, %2};" : "=l"(r) : "f"(x), "f"(y));
    return r;
}
__device__ __forceinline__ float2 unpack2(unsigned long long v) {
    float2 r;
    asm("mov.b64 {%0, %1}, %2;" : "=f"(r.x), "=f"(r.y) : "l"(v));
    return r;
}
__device__ __forceinline__ void ffma2(unsigned long long& d,
                                      unsigned long long a,
                                      unsigned long long b) {
    asm("fma.rn.f32x2 %0, %1, %2, %0;" : "+l"(d) : "l"(a), "l"(b));
}

// ---------------------------------------------------------------------------
// Mask dtype probe: decide how the bool noise_mask was serialized.
// u8 packing  -> many 32-bit words with "weird" nonzero patterns
// i32 (0/1)   -> words are 0 or 1
// f32 (0/1.0) -> words are 0 or 0x3F800000
// ---------------------------------------------------------------------------
__global__ void probe_mask_kernel(const unsigned int* __restrict__ w) {
    __shared__ int s_other, s_f1, s_i1;
    if (threadIdx.x == 0) { s_other = 0; s_f1 = 0; s_i1 = 0; }
    __syncthreads();
    int lo = 0, lf = 0, li = 0;
    for (int i = threadIdx.x; i < 65536; i += blockDim.x) {
        unsigned v = w[i];
        if (v == 0u) continue;
        else if (v == 1u) li++;
        else if (v == 0x3F800000u) lf++;
        else lo++;
    }
    atomicAdd(&s_other, lo);
    atomicAdd(&s_f1, lf);
    atomicAdd(&s_i1, li);
    __syncthreads();
    if (threadIdx.x == 0) {
        int mode;
        if (s_other > 1024) mode = 0;          // packed bytes
        else if (s_f1 >= s_i1) mode = 2;       // float 0/1
        else mode = 1;                         // int32 0/1
        g_mask_mode = mode;
    }
}

// ---------------------------------------------------------------------------
// popular = mean(likes, axis=0)
// ---------------------------------------------------------------------------
__global__ void popular_partial_kernel(const float* __restrict__ likes,
                                       float* __restrict__ part) {
    int i = blockIdx.x * 256 + threadIdx.x;
    if (i >= NITEMS) return;
    int r0 = blockIdx.y * 128;
    float s = 0.f;
    #pragma unroll 8
    for (int r = 0; r < 128; r++)
        s += likes[(size_t)(r0 + r) * NITEMS + i];
    part[blockIdx.y * NITEMS + i] = s;
}

__global__ void popular_reduce_kernel(const float* __restrict__ part,
                                      float* __restrict__ out_pop) {
    int i = blockIdx.x * 256 + threadIdx.x;
    if (i >= NITEMS) return;
    float s = 0.f;
    #pragma unroll
    for (int c = 0; c < 16; c++) s += part[c * NITEMS + i];
    out_pop[i] = s * (1.0f / (float)BATCH);
}

// ---------------------------------------------------------------------------
// L2 normalize rows of E (tf.nn.l2_normalize semantics, EPS=1e-12)
// ---------------------------------------------------------------------------
__global__ void norm_kernel(const float* __restrict__ E, float* __restrict__ Nrm) {
    int row = blockIdx.x;
    int t = threadIdx.x;                // 128 threads, one float4 each (EMB=512)
    float4 v = reinterpret_cast<const float4*>(E + (size_t)row * EMB)[t];
    float ss = v.x * v.x + v.y * v.y + v.z * v.z + v.w * v.w;
    #pragma unroll
    for (int o = 16; o > 0; o >>= 1)
        ss += __shfl_xor_sync(0xFFFFFFFFu, ss, o);
    __shared__ float ws[4];
    if ((t & 31) == 0) ws[t >> 5] = ss;
    __syncthreads();
    float tot = ws[0] + ws[1] + ws[2] + ws[3];
    float inv = rsqrtf(fmaxf(tot, 1e-12f));
    v.x *= inv; v.y *= inv; v.z *= inv; v.w *= inv;
    reinterpret_cast<float4*>(Nrm + (size_t)row * EMB)[t] = v;
}

// ---------------------------------------------------------------------------
// Tiled fp32 GEMM with FFMA2 micro-kernel.
//   C[M,N] = act(A[M,K] @ B[K,N] + bias)
//   TRANSB: B is given as W[N][K] (row-major) -> computes A @ W^T
//   MASKED: A element zeroed where mask nonzero (gemm1 denoising)
// Tile 128x128x16, 256 threads, 8x8 per thread (cols as 4 f32x2 pairs).
// M % 128 == 0 and K % 16 == 0 assumed (true for all calls); N is guarded.
// ---------------------------------------------------------------------------
enum { ACT_RELU = 0, ACT_SIG = 1, ACT_NEG = 2 };
#define BM 128
#define BN 128
#define BK 16

template<int ACT, bool MASKED, bool TRANSB, bool HAS_BIAS>
__global__ __launch_bounds__(256, 2)
void gemm_kernel(const float* __restrict__ A, const void* __restrict__ mask,
                 const float* __restrict__ W, const float* __restrict__ bias,
                 float* __restrict__ C, int M, int N, int K) {
    __shared__ float  As[BK][BM + 4];
    __shared__ float2 Ws2[BK][BN / 2];

    const int tid = threadIdx.x;
    const int tx = tid & 15;       // column group
    const int ty = tid >> 4;       // row group
    const int m0 = blockIdx.y * BM;
    const int n0 = blockIdx.x * BN;

    int mmode = 0;
    if (MASKED) mmode = g_mask_mode;

    unsigned long long acc[8][4];
    #pragma unroll
    for (int i = 0; i < 8; i++) {
        #pragma unroll
        for (int j = 0; j < 4; j++) acc[i][j] = 0ull;
    }

    for (int k0 = 0; k0 < K; k0 += BK) {
        // ---- load A tile [BM x BK] -> As[k][m] (transposed) ----
        #pragma unroll
        for (int u = 0; u < 2; u++) {
            int idx = tid + u * 256;          // 0..511
            int r   = idx >> 2;               // row 0..127
            int c4  = (idx & 3) << 2;         // k offset 0,4,8,12
            size_t ge = (size_t)(m0 + r) * K + (k0 + c4);
            float4 v = *reinterpret_cast<const float4*>(A + ge);
            if (MASKED) {
                if (mmode == 0) {
                    uchar4 mv = *reinterpret_cast<const uchar4*>(
                        (const unsigned char*)mask + ge);
                    if (mv.x) v.x = 0.f;
                    if (mv.y) v.y = 0.f;
                    if (mv.z) v.z = 0.f;
                    if (mv.w) v.w = 0.f;
                } else if (mmode == 1) {
                    int4 mv = *reinterpret_cast<const int4*>((const int*)mask + ge);
                    if (mv.x) v.x = 0.f;
                    if (mv.y) v.y = 0.f;
                    if (mv.z) v.z = 0.f;
                    if (mv.w) v.w = 0.f;
                } else {
                    float4 mv = *reinterpret_cast<const float4*>((const float*)mask + ge);
                    if (mv.x != 0.f) v.x = 0.f;
                    if (mv.y != 0.f) v.y = 0.f;
                    if (mv.z != 0.f) v.z = 0.f;
                    if (mv.w != 0.f) v.w = 0.f;
                }
            }
            As[c4 + 0][r] = v.x;
            As[c4 + 1][r] = v.y;
            As[c4 + 2][r] = v.z;
            As[c4 + 3][r] = v.w;
        }
        // ---- load B tile [BK x BN] -> Ws2[k][n-pair] ----
        if (!TRANSB) {
            #pragma unroll
            for (int u = 0; u < 2; u++) {
                int idx = tid + u * 256;
                int r = idx >> 5;              // k row 0..15
                int c = (idx & 31) << 2;       // n offset 0..124
                int n = n0 + c;
                float4 v;
                if (n + 4 <= N)
                    v = *reinterpret_cast<const float4*>(W + (size_t)(k0 + r) * N + n);
                else
                    v = make_float4(0.f, 0.f, 0.f, 0.f);
                Ws2[r][(c >> 1) + 0] = make_float2(v.x, v.y);
                Ws2[r][(c >> 1) + 1] = make_float2(v.z, v.w);
            }
        } else {
            float* Wsf = reinterpret_cast<float*>(Ws2);
            #pragma unroll
            for (int u = 0; u < 2; u++) {
                int idx = tid + u * 256;
                int r  = idx >> 2;             // n offset 0..127
                int c4 = (idx & 3) << 2;       // k offset 0,4,8,12
                float4 v = *reinterpret_cast<const float4*>(
                    W + (size_t)(n0 + r) * K + (k0 + c4));
                Wsf[(c4 + 0) * BN + r] = v.x;
                Wsf[(c4 + 1) * BN + r] = v.y;
                Wsf[(c4 + 2) * BN + r] = v.z;
                Wsf[(c4 + 3) * BN + r] = v.w;
            }
        }
        __syncthreads();

        // ---- micro-kernel: 8 rows x 4 col-pairs, FFMA2 ----
        #pragma unroll
        for (int kk = 0; kk < BK; kk++) {
            unsigned long long a2[8], b2[4];
            #pragma unroll
            for (int i = 0; i < 8; i++) {
                float a = As[kk][ty * 8 + i];
                a2[i] = pack2(a, a);
            }
            #pragma unroll
            for (int j = 0; j < 4; j++)
                b2[j] = *reinterpret_cast<const unsigned long long*>(
                    &Ws2[kk][tx + 16 * j]);
            #pragma unroll
            for (int i = 0; i < 8; i++) {
                #pragma unroll
                for (int j = 0; j < 4; j++) ffma2(acc[i][j], a2[i], b2[j]);
            }
        }
        __syncthreads();
    }

    // ---- epilogue ----
    #pragma unroll
    for (int i = 0; i < 8; i++) {
        int m = m0 + ty * 8 + i;
        #pragma unroll
        for (int j = 0; j < 4; j++) {
            int col = n0 + tx * 2 + 32 * j;
            if (col + 2 <= N) {
                float2 c = unpack2(acc[i][j]);
                if (HAS_BIAS) {
                    float2 bb = *reinterpret_cast<const float2*>(bias + col);
                    c.x += bb.x;
                    c.y += bb.y;
                }
                if (ACT == ACT_RELU) {
                    c.x = fmaxf(c.x, 0.f);
                    c.y = fmaxf(c.y, 0.f);
                } else if (ACT == ACT_SIG) {
                    c.x = 1.f / (1.f + __expf(-c.x));
                    c.y = 1.f / (1.f + __expf(-c.y));
                } else {  // ACT_NEG: user_sim = -cosine
                    c.x = -c.x;
                    c.y = -c.y;
                }
                *reinterpret_cast<float2*>(C + (size_t)m * N + col) = c;
            }
        }
    }
}

// ---------------------------------------------------------------------------
// Launch: full pipeline on the default stream (graph-capturable, no allocs)
// ---------------------------------------------------------------------------
extern "C" void kernel_launch(void* const* d_in, const int* in_sizes, int n_in,
                              void* d_out, int out_size) {
    // metadata order: users, likes, noise_mask, enc_w1, enc_b1, enc_w2, enc_b2,
    //                 lk_w1, lk_b1, lk_w2, lk_b2, rc_w1, rc_b1, rc_w2, rc_b2
    const float* likes  = (const float*)d_in[1];
    const void*  nmask  = d_in[2];
    const float* enc_w1 = (const float*)d_in[3];
    const float* enc_b1 = (const float*)d_in[4];
    const float* enc_w2 = (const float*)d_in[5];
    const float* enc_b2 = (const float*)d_in[6];
    const float* lk_w1  = (const float*)d_in[7];
    const float* lk_b1  = (const float*)d_in[8];
    const float* lk_w2  = (const float*)d_in[9];
    const float* lk_b2  = (const float*)d_in[10];
    const float* rc_w1  = (const float*)d_in[11];
    const float* rc_b1  = (const float*)d_in[12];
    const float* rc_w2  = (const float*)d_in[13];
    const float* rc_b2  = (const float*)d_in[14];

    float* out       = (float*)d_out;
    float* out_likes = out;                                          // [B, I]
    float* out_sim   = out_likes + (size_t)BATCH * NITEMS;           // [B, B]
    float* out_rec   = out_sim + (size_t)BATCH * BATCH;              // [B, I]
    float* out_pop   = out_rec + (size_t)BATCH * NITEMS;             // [I]

    float *H, *E, *Nrm, *part;
    cudaGetSymbolAddress((void**)&H, g_H);
    cudaGetSymbolAddress((void**)&E, g_E);
    cudaGetSymbolAddress((void**)&Nrm, g_Nrm);
    cudaGetSymbolAddress((void**)&part, g_part);

    const int gx_items = (NITEMS + BN - 1) / BN;  // 157
    const int gy = BATCH / BM;                    // 16

    // mask dtype probe (writes g_mask_mode)
    probe_mask_kernel<<<1, 256>>>((const unsigned int*)nmask);

    // popular = mean(likes, axis=0)
    popular_partial_kernel<<<dim3((NITEMS + 255) / 256, 16), 256>>>(likes, part);
    popular_reduce_kernel<<<(NITEMS + 255) / 256, 256>>>(part, out_pop);

    // encoder: H = relu(noisy_likes @ enc_w1 + b1)   [2048 x 1024], K=20000
    gemm_kernel<ACT_RELU, true, false, true>
        <<<dim3(HID / BN, gy), 256>>>(likes, nmask, enc_w1, enc_b1, H,
                                      BATCH, HID, NITEMS);
    // E = relu(H @ enc_w2 + b2)                      [2048 x 512]
    gemm_kernel<ACT_RELU, false, false, true>
        <<<dim3(EMB / BN, gy), 256>>>(H, nullptr, enc_w2, enc_b2, E,
                                      BATCH, EMB, HID);
    // l2 normalize
    norm_kernel<<<BATCH, 128>>>(E, Nrm);

    // user_sim = -(Nrm @ Nrm^T)                      [2048 x 2048]
    gemm_kernel<ACT_NEG, false, true, false>
        <<<dim3(BATCH / BN, gy), 256>>>(Nrm, nullptr, Nrm, nullptr, out_sim,
                                        BATCH, BATCH, EMB);

    // likes head
    gemm_kernel<ACT_RELU, false, false, true>
        <<<dim3(HID / BN, gy), 256>>>(E, nullptr, lk_w1, lk_b1, H,
                                      BATCH, HID, EMB);
    gemm_kernel<ACT_SIG, false, false, true>
        <<<dim3(gx_items, gy), 256>>>(H, nullptr, lk_w2, lk_b2, out_likes,
                                      BATCH, NITEMS, HID);

    // rec head
    gemm_kernel<ACT_RELU, false, false, true>
        <<<dim3(HID / BN, gy), 256>>>(E, nullptr, rc_w1, rc_b1, H,
                                      BATCH, HID, EMB);
    gemm_kernel<ACT_SIG, false, false, true>
        <<<dim3(gx_items, gy), 256>>>(H, nullptr, rc_w2, rc_b2, out_rec,
                                      BATCH, NITEMS, HID);
}

// round 3
// speedup vs baseline: 4.7201x; 4.7201x over previous
#include <cuda_runtime.h>
#include <cuda_fp16.h>
#include <cstdint>

// Problem constants
#define BATCH  2048
#define NITEMS 20000
#define KPAD   20032   // NITEMS padded to multiple of 64
#define EMB    512
#define HID    1024    // 2*D

// ---------------------------------------------------------------------------
// Scratch (no allocations -> __device__ globals), all fp16 GEMM operands
// ---------------------------------------------------------------------------
__device__ __half g_noisyh[(size_t)BATCH * KPAD];    // masked likes fp16, padded
__device__ __half g_W1h[(size_t)HID * KPAD];         // enc_w1^T [1024][20032]
__device__ __half g_W2h[(size_t)EMB * HID];          // enc_w2^T [512][1024]
__device__ __half g_W3h[(size_t)HID * EMB];          // lk_w1^T  [1024][512]
__device__ __half g_W4h[(size_t)NITEMS * HID];       // lk_w2^T  [20000][1024]
__device__ __half g_W5h[(size_t)HID * EMB];          // rc_w1^T
__device__ __half g_W6h[(size_t)NITEMS * HID];       // rc_w2^T
__device__ __half g_Hh[(size_t)BATCH * HID];         // hidden fp16
__device__ float  g_E[(size_t)BATCH * EMB];          // embed f32
__device__ __half g_Eh[(size_t)BATCH * EMB];         // embed fp16
__device__ __half g_Nrmh[(size_t)BATCH * EMB];       // normalized fp16
__device__ float  g_part[16 * NITEMS];
__device__ int    g_mask_mode;  // 0=u8, 1=i32, 2=f32

// ---------------------------------------------------------------------------
// PTX helpers (all arch-generic: sm_80-era instructions)
// ---------------------------------------------------------------------------
__device__ __forceinline__ uint32_t smem_u32(const void* p) {
    uint32_t a;
    asm("{ .reg .u64 t; cvta.to.shared.u64 t, %1; cvt.u32.u64 %0, t; }"
        : "=r"(a) : "l"(p));
    return a;
}
__device__ __forceinline__ void cp16(uint32_t dst, const void* src, int sz) {
    asm volatile("cp.async.cg.shared.global [%0], [%1], 16, %2;"
        :: "r"(dst), "l"(src), "r"(sz));
}
#define CP_COMMIT() asm volatile("cp.async.commit_group;" ::: "memory")
#define CP_WAIT(n)  asm volatile("cp.async.wait_group %0;" :: "n"(n) : "memory")

#define LDSM_X4(r, addr) \
    asm volatile("ldmatrix.sync.aligned.m8n8.x4.shared.b16 {%0,%1,%2,%3}, [%4];" \
        : "=r"((r)[0]), "=r"((r)[1]), "=r"((r)[2]), "=r"((r)[3]) : "r"(addr))

__device__ __forceinline__ void mma16816(float* d, const uint32_t* a,
                                         uint32_t b0, uint32_t b1) {
    asm volatile(
        "mma.sync.aligned.m16n8k16.row.col.f32.f16.f16.f32 "
        "{%0,%1,%2,%3}, {%4,%5,%6,%7}, {%8,%9}, {%0,%1,%2,%3};"
        : "+f"(d[0]), "+f"(d[1]), "+f"(d[2]), "+f"(d[3])
        : "r"(a[0]), "r"(a[1]), "r"(a[2]), "r"(a[3]), "r"(b0), "r"(b1));
}

// ---------------------------------------------------------------------------
// Small kernels
// ---------------------------------------------------------------------------
__global__ void probe_mask_kernel(const unsigned int* __restrict__ w) {
    __shared__ int s_other, s_f1, s_i1;
    if (threadIdx.x == 0) { s_other = 0; s_f1 = 0; s_i1 = 0; }
    __syncthreads();
    int lo = 0, lf = 0, li = 0;
    for (int i = threadIdx.x; i < 65536; i += blockDim.x) {
        unsigned v = w[i];
        if (v == 0u) continue;
        else if (v == 1u) li++;
        else if (v == 0x3F800000u) lf++;
        else lo++;
    }
    atomicAdd(&s_other, lo); atomicAdd(&s_f1, lf); atomicAdd(&s_i1, li);
    __syncthreads();
    if (threadIdx.x == 0) {
        int mode;
        if (s_other > 1024) mode = 0;
        else if (s_f1 >= s_i1) mode = 2;
        else mode = 1;
        g_mask_mode = mode;
    }
}

// noisy = where(mask, 0, likes) -> fp16, padded [BATCH][KPAD]
__global__ void premask_half_kernel(const float* __restrict__ likes,
                                    const void* __restrict__ mask,
                                    __half* __restrict__ out) {
    const int mode = g_mask_mode;
    int row = blockIdx.y;
    int c4 = (blockIdx.x * 256 + threadIdx.x) * 4;
    if (c4 >= KPAD) return;
    __half2 h0, h1;
    if (c4 < NITEMS) {
        size_t e = (size_t)row * NITEMS + c4;
        float4 v = *reinterpret_cast<const float4*>(likes + e);
        if (mode == 0) {
            uchar4 m = *reinterpret_cast<const uchar4*>((const unsigned char*)mask + e);
            if (m.x) v.x = 0.f;
            if (m.y) v.y = 0.f;
            if (m.z) v.z = 0.f;
            if (m.w) v.w = 0.f;
        } else if (mode == 1) {
            int4 m = *reinterpret_cast<const int4*>((const int*)mask + e);
            if (m.x) v.x = 0.f;
            if (m.y) v.y = 0.f;
            if (m.z) v.z = 0.f;
            if (m.w) v.w = 0.f;
        } else {
            float4 m = *reinterpret_cast<const float4*>((const float*)mask + e);
            if (m.x != 0.f) v.x = 0.f;
            if (m.y != 0.f) v.y = 0.f;
            if (m.z != 0.f) v.z = 0.f;
            if (m.w != 0.f) v.w = 0.f;
        }
        h0 = __floats2half2_rn(v.x, v.y);
        h1 = __floats2half2_rn(v.z, v.w);
    } else {
        h0 = __floats2half2_rn(0.f, 0.f);
        h1 = h0;
    }
    __half2* dst = reinterpret_cast<__half2*>(out + (size_t)row * KPAD + c4);
    dst[0] = h0;
    dst[1] = h1;
}

__global__ void popular_partial_kernel(const float* __restrict__ likes,
                                       float* __restrict__ part) {
    int i = blockIdx.x * 256 + threadIdx.x;
    if (i >= NITEMS) return;
    int r0 = blockIdx.y * 128;
    float s = 0.f;
    #pragma unroll 8
    for (int r = 0; r < 128; r++)
        s += likes[(size_t)(r0 + r) * NITEMS + i];
    part[blockIdx.y * NITEMS + i] = s;
}

__global__ void popular_reduce_kernel(const float* __restrict__ part,
                                      float* __restrict__ out_pop) {
    int i = blockIdx.x * 256 + threadIdx.x;
    if (i >= NITEMS) return;
    float s = 0.f;
    #pragma unroll
    for (int c = 0; c < 16; c++) s += part[c * NITEMS + i];
    out_pop[i] = s * (1.0f / (float)BATCH);
}

// per-row l2 normalize; emit fp16 normalized AND fp16 copy of E
__global__ void norm_half_kernel(const float* __restrict__ E,
                                 __half* __restrict__ Nrmh,
                                 __half* __restrict__ Eh) {
    int row = blockIdx.x;
    int t = threadIdx.x;   // 128 threads, EMB=512 -> one float4 each
    float4 v = reinterpret_cast<const float4*>(E + (size_t)row * EMB)[t];
    float ss = v.x * v.x + v.y * v.y + v.z * v.z + v.w * v.w;
    #pragma unroll
    for (int o = 16; o > 0; o >>= 1)
        ss += __shfl_xor_sync(0xFFFFFFFFu, ss, o);
    __shared__ float ws[4];
    if ((t & 31) == 0) ws[t >> 5] = ss;
    __syncthreads();
    float tot = ws[0] + ws[1] + ws[2] + ws[3];
    float inv = rsqrtf(fmaxf(tot, 1e-12f));
    __half2* eh = reinterpret_cast<__half2*>(Eh + (size_t)row * EMB + t * 4);
    eh[0] = __floats2half2_rn(v.x, v.y);
    eh[1] = __floats2half2_rn(v.z, v.w);
    __half2* nh = reinterpret_cast<__half2*>(Nrmh + (size_t)row * EMB + t * 4);
    nh[0] = __floats2half2_rn(v.x * inv, v.y * inv);
    nh[1] = __floats2half2_rn(v.z * inv, v.w * inv);
}

// transpose + convert: in f32 [R][C] -> out fp16 [C][Rp], zero for r >= R
__global__ void transpose_half_kernel(const float* __restrict__ in,
                                      __half* __restrict__ out,
                                      int R, int C, int Rp) {
    __shared__ float t[32][33];
    int c0 = blockIdx.x * 32, r0 = blockIdx.y * 32;
    int x = threadIdx.x, y = threadIdx.y;
    #pragma unroll
    for (int i = 0; i < 32; i += 8) {
        int r = r0 + y + i, c = c0 + x;
        t[y + i][x] = (r < R && c < C) ? in[(size_t)r * C + c] : 0.f;
    }
    __syncthreads();
    #pragma unroll
    for (int i = 0; i < 32; i += 8) {
        int cc = c0 + y + i, rr = r0 + x;
        if (cc < C && rr < Rp)
            out[(size_t)cc * Rp + rr] = __float2half_rn(t[x][y + i]);
    }
}

// ---------------------------------------------------------------------------
// fp16 tensor-core GEMM: C[M,N] = act(A[M,K] @ Bt[N,K]^T + bias)
//   A: fp16 [M][lda] K-major;  Bt: fp16 [N][ldb] K-major.
//   CTA tile 128x128, BK=64, 4-stage cp.async, 8 warps (2m x 4n, 64x32 each),
//   mma.sync.m16n8k16 + ldmatrix (arch-generic PTX -> works on compute_103).
// ---------------------------------------------------------------------------
enum { ACT_RELU = 0, ACT_SIG = 1, ACT_NEG = 2 };
#define BK 64
#define NSTAGE 4
#define ASZ 16384                 // 128 rows * 128B
#define SSZ 32768                 // A + B per stage

template<int ACT, bool HAS_BIAS, bool OUT_HALF>
__global__ __launch_bounds__(256, 1)
void hmma_gemm(const __half* __restrict__ A, const __half* __restrict__ Bt,
               const float* __restrict__ bias, void* __restrict__ Cout,
               int M, int N, int K, int lda, int ldb) {
    extern __shared__ __align__(128) char smem[];
    const uint32_t sbase = smem_u32(smem);

    const int tid = threadIdx.x;
    const int lane = tid & 31, wid = tid >> 5;
    const int wm = (wid & 1) * 64;        // warp m offset in tile
    const int wn = (wid >> 1) * 32;       // warp n offset in tile
    const int m0 = blockIdx.x * 128;
    const int n0 = blockIdx.y * 128;
    const int nch = K / BK;

    float acc[4][4][4];
    #pragma unroll
    for (int i = 0; i < 4; i++)
        #pragma unroll
        for (int j = 0; j < 4; j++)
            #pragma unroll
            for (int q = 0; q < 4; q++) acc[i][j][q] = 0.f;

    // ---- stage loader ----
    auto load_stage = [&](int ch, int st) {
        const int k0 = ch * BK;
        const uint32_t sA = sbase + st * SSZ;
        const uint32_t sB = sA + ASZ;
        #pragma unroll
        for (int u = 0; u < 4; u++) {
            int idx = tid + u * 256;
            int r = idx >> 3, c = idx & 7;
            const __half* src = A + (size_t)(m0 + r) * lda + k0 + c * 8;
            cp16(sA + r * 128 + ((c ^ (r & 7)) << 4), src, 16);
        }
        #pragma unroll
        for (int u = 0; u < 4; u++) {
            int idx = tid + u * 256;
            int r = idx >> 3, c = idx & 7;
            int n = n0 + r;
            const __half* src = Bt + (size_t)n * ldb + k0 + c * 8;
            cp16(sB + r * 128 + ((c ^ (r & 7)) << 4), src, (n < N) ? 16 : 0);
        }
        CP_COMMIT();
    };

    // ldmatrix lane addressing (swizzle bits constant per lane)
    const int aRow = wm + (lane & 15);
    const int aKsel = lane >> 4;            // 0/1 -> +16B within 32B k16
    const int bRow = wn + ((lane >> 4) << 3) + (lane & 7);
    const int bKsel = (lane >> 3) & 1;
    const int swz = lane & 7;

    load_stage(0, 0);
    load_stage(1, 1);
    load_stage(2, 2);

    for (int i = 0; i < nch; i++) {
        const int j = i + 3;
        if (j < nch) load_stage(j, j & 3);
        else         CP_COMMIT();           // empty group keeps wait count aligned
        CP_WAIT(3);
        __syncthreads();

        const uint32_t sA = sbase + (i & 3) * SSZ;
        const uint32_t sB = sA + ASZ;
        #pragma unroll
        for (int kk = 0; kk < 4; kk++) {
            uint32_t a[4][4], b[2][4];
            const uint32_t aByte = ((2 * kk + aKsel) ^ swz) << 4;
            const uint32_t bByte = ((2 * kk + bKsel) ^ swz) << 4;
            #pragma unroll
            for (int mf = 0; mf < 4; mf++)
                LDSM_X4(a[mf], sA + (aRow + 16 * mf) * 128 + aByte);
            #pragma unroll
            for (int nf2 = 0; nf2 < 2; nf2++)
                LDSM_X4(b[nf2], sB + (bRow + 16 * nf2) * 128 + bByte);
            #pragma unroll
            for (int mf = 0; mf < 4; mf++)
                #pragma unroll
                for (int nf = 0; nf < 4; nf++)
                    mma16816(acc[mf][nf], a[mf],
                             b[nf >> 1][(nf & 1) * 2],
                             b[nf >> 1][(nf & 1) * 2 + 1]);
        }
        __syncthreads();
    }

    // ---- epilogue ----
    #pragma unroll
    for (int mf = 0; mf < 4; mf++) {
        const int row = m0 + wm + mf * 16 + (lane >> 2);
        #pragma unroll
        for (int nf = 0; nf < 4; nf++) {
            const int col = n0 + wn + nf * 8 + 2 * (lane & 3);
            if (col >= N) continue;
            float2 lo = make_float2(acc[mf][nf][0], acc[mf][nf][1]);
            float2 hi = make_float2(acc[mf][nf][2], acc[mf][nf][3]);
            if (HAS_BIAS) {
                float2 bb = *reinterpret_cast<const float2*>(bias + col);
                lo.x += bb.x; lo.y += bb.y;
                hi.x += bb.x; hi.y += bb.y;
            }
            if (ACT == ACT_RELU) {
                lo.x = fmaxf(lo.x, 0.f); lo.y = fmaxf(lo.y, 0.f);
                hi.x = fmaxf(hi.x, 0.f); hi.y = fmaxf(hi.y, 0.f);
            } else if (ACT == ACT_SIG) {
                lo.x = 1.f / (1.f + __expf(-lo.x));
                lo.y = 1.f / (1.f + __expf(-lo.y));
                hi.x = 1.f / (1.f + __expf(-hi.x));
                hi.y = 1.f / (1.f + __expf(-hi.y));
            } else {
                lo.x = -lo.x; lo.y = -lo.y;
                hi.x = -hi.x; hi.y = -hi.y;
            }
            if (OUT_HALF) {
                __half* C = (__half*)Cout;
                *reinterpret_cast<__half2*>(C + (size_t)row * N + col) =
                    __floats2half2_rn(lo.x, lo.y);
                *reinterpret_cast<__half2*>(C + (size_t)(row + 8) * N + col) =
                    __floats2half2_rn(hi.x, hi.y);
            } else {
                float* C = (float*)Cout;
                *reinterpret_cast<float2*>(C + (size_t)row * N + col) = lo;
                *reinterpret_cast<float2*>(C + (size_t)(row + 8) * N + col) = hi;
            }
        }
    }
}

// ---------------------------------------------------------------------------
// Launch
// ---------------------------------------------------------------------------
extern "C" void kernel_launch(void* const* d_in, const int* in_sizes, int n_in,
                              void* d_out, int out_size) {
    const float* likes  = (const float*)d_in[1];
    const void*  nmask  = d_in[2];
    const float* enc_w1 = (const float*)d_in[3];
    const float* enc_b1 = (const float*)d_in[4];
    const float* enc_w2 = (const float*)d_in[5];
    const float* enc_b2 = (const float*)d_in[6];
    const float* lk_w1  = (const float*)d_in[7];
    const float* lk_b1  = (const float*)d_in[8];
    const float* lk_w2  = (const float*)d_in[9];
    const float* lk_b2  = (const float*)d_in[10];
    const float* rc_w1  = (const float*)d_in[11];
    const float* rc_b1  = (const float*)d_in[12];
    const float* rc_w2  = (const float*)d_in[13];
    const float* rc_b2  = (const float*)d_in[14];

    float* out       = (float*)d_out;
    float* out_likes = out;
    float* out_sim   = out_likes + (size_t)BATCH * NITEMS;
    float* out_rec   = out_sim + (size_t)BATCH * BATCH;
    float* out_pop   = out_rec + (size_t)BATCH * NITEMS;

    __half *noisyh, *W1h, *W2h, *W3h, *W4h, *W5h, *W6h, *Hh, *Eh, *Nrmh;
    float *E, *part;
    cudaGetSymbolAddress((void**)&noisyh, g_noisyh);
    cudaGetSymbolAddress((void**)&W1h, g_W1h);
    cudaGetSymbolAddress((void**)&W2h, g_W2h);
    cudaGetSymbolAddress((void**)&W3h, g_W3h);
    cudaGetSymbolAddress((void**)&W4h, g_W4h);
    cudaGetSymbolAddress((void**)&W5h, g_W5h);
    cudaGetSymbolAddress((void**)&W6h, g_W6h);
    cudaGetSymbolAddress((void**)&Hh, g_Hh);
    cudaGetSymbolAddress((void**)&E, g_E);
    cudaGetSymbolAddress((void**)&Eh, g_Eh);
    cudaGetSymbolAddress((void**)&Nrmh, g_Nrmh);
    cudaGetSymbolAddress((void**)&part, g_part);

    const int smem = NSTAGE * SSZ;  // 128KB
    cudaFuncSetAttribute(hmma_gemm<ACT_RELU, true, true>,
                         cudaFuncAttributeMaxDynamicSharedMemorySize, smem);
    cudaFuncSetAttribute(hmma_gemm<ACT_RELU, true, false>,
                         cudaFuncAttributeMaxDynamicSharedMemorySize, smem);
    cudaFuncSetAttribute(hmma_gemm<ACT_SIG, true, false>,
                         cudaFuncAttributeMaxDynamicSharedMemorySize, smem);
    cudaFuncSetAttribute(hmma_gemm<ACT_NEG, false, false>,
                         cudaFuncAttributeMaxDynamicSharedMemorySize, smem);

    // mask probe + fp16 denoised input + popularity
    probe_mask_kernel<<<1, 256>>>((const unsigned int*)nmask);
    premask_half_kernel<<<dim3((KPAD / 4 + 255) / 256, BATCH), 256>>>(
        likes, nmask, noisyh);
    popular_partial_kernel<<<dim3((NITEMS + 255) / 256, 16), 256>>>(likes, part);
    popular_reduce_kernel<<<(NITEMS + 255) / 256, 256>>>(part, out_pop);

    // weight transposes -> fp16 K-major
    dim3 tb(32, 8);
    transpose_half_kernel<<<dim3(HID / 32, KPAD / 32), tb>>>(
        enc_w1, W1h, NITEMS, HID, KPAD);
    transpose_half_kernel<<<dim3(EMB / 32, HID / 32), tb>>>(
        enc_w2, W2h, HID, EMB, HID);
    transpose_half_kernel<<<dim3(HID / 32, EMB / 32), tb>>>(
        lk_w1, W3h, EMB, HID, EMB);
    transpose_half_kernel<<<dim3((NITEMS + 31) / 32, HID / 32), tb>>>(
        lk_w2, W4h, HID, NITEMS, HID);
    transpose_half_kernel<<<dim3(HID / 32, EMB / 32), tb>>>(
        rc_w1, W5h, EMB, HID, EMB);
    transpose_half_kernel<<<dim3((NITEMS + 31) / 32, HID / 32), tb>>>(
        rc_w2, W6h, HID, NITEMS, HID);

    // encoder
    hmma_gemm<ACT_RELU, true, true><<<dim3(BATCH / 128, HID / 128), 256, smem>>>(
        noisyh, W1h, enc_b1, Hh, BATCH, HID, KPAD, KPAD, KPAD);
    hmma_gemm<ACT_RELU, true, false><<<dim3(BATCH / 128, EMB / 128), 256, smem>>>(
        Hh, W2h, enc_b2, E, BATCH, EMB, HID, HID, HID);
    norm_half_kernel<<<BATCH, 128>>>(E, Nrmh, Eh);

    // user_sim = -(Nrm @ Nrm^T)
    hmma_gemm<ACT_NEG, false, false><<<dim3(BATCH / 128, BATCH / 128), 256, smem>>>(
        Nrmh, Nrmh, nullptr, out_sim, BATCH, BATCH, EMB, EMB, EMB);

    // likes head
    hmma_gemm<ACT_RELU, true, true><<<dim3(BATCH / 128, HID / 128), 256, smem>>>(
        Eh, W3h, lk_b1, Hh, BATCH, HID, EMB, EMB, EMB);
    hmma_gemm<ACT_SIG, true, false>
        <<<dim3(BATCH / 128, (NITEMS + 127) / 128), 256, smem>>>(
        Hh, W4h, lk_b2, out_likes, BATCH, NITEMS, HID, HID, HID);

    // rec head
    hmma_gemm<ACT_RELU, true, true><<<dim3(BATCH / 128, HID / 128), 256, smem>>>(
        Eh, W5h, rc_b1, Hh, BATCH, HID, EMB, EMB, EMB);
    hmma_gemm<ACT_SIG, true, false>
        <<<dim3(BATCH / 128, (NITEMS + 127) / 128), 256, smem>>>(
        Hh, W6h, rc_b2, out_rec, BATCH, NITEMS, HID, HID, HID);
}

// round 4
// speedup vs baseline: 5.5667x; 1.1793x over previous
#include <cuda_runtime.h>
#include <cuda_fp16.h>
#include <cstdint>

// Problem constants
#define BATCH  2048
#define NITEMS 20000
#define KPAD   20032   // NITEMS padded to multiple of 64
#define EMB    512
#define HID    1024    // 2*D

// ---------------------------------------------------------------------------
// Scratch (no allocations -> __device__ globals), all fp16 GEMM operands
// ---------------------------------------------------------------------------
__device__ __half g_noisyh[(size_t)BATCH * KPAD];    // masked likes fp16, padded
__device__ __half g_W1h[(size_t)HID * KPAD];         // enc_w1^T [1024][20032]
__device__ __half g_W2h[(size_t)EMB * HID];          // enc_w2^T [512][1024]
__device__ __half g_W3h[(size_t)HID * EMB];          // lk_w1^T  [1024][512]
__device__ __half g_W4h[(size_t)NITEMS * HID];       // lk_w2^T  [20000][1024]
__device__ __half g_W5h[(size_t)HID * EMB];          // rc_w1^T
__device__ __half g_W6h[(size_t)NITEMS * HID];       // rc_w2^T
__device__ __half g_Hh[(size_t)BATCH * HID];         // hidden fp16
__device__ float  g_E[(size_t)BATCH * EMB];          // embed f32
__device__ __half g_Eh[(size_t)BATCH * EMB];         // embed fp16
__device__ __half g_Nrmh[(size_t)BATCH * EMB];       // normalized fp16
__device__ float  g_part[16 * NITEMS];
__device__ int    g_mask_mode;  // 0=u8, 1=i32, 2=f32

// ---------------------------------------------------------------------------
// PTX helpers (arch-generic sm_80-era instructions; no sm_103a-only ops)
// ---------------------------------------------------------------------------
__device__ __forceinline__ uint32_t smem_u32(const void* p) {
    uint32_t a;
    asm("{ .reg .u64 t; cvta.to.shared.u64 t, %1; cvt.u32.u64 %0, t; }"
        : "=r"(a) : "l"(p));
    return a;
}
__device__ __forceinline__ void cp16(uint32_t dst, const void* src, int sz) {
    asm volatile("cp.async.cg.shared.global [%0], [%1], 16, %2;"
        :: "r"(dst), "l"(src), "r"(sz));
}
#define CP_COMMIT() asm volatile("cp.async.commit_group;" ::: "memory")
#define CP_WAIT(n)  asm volatile("cp.async.wait_group %0;" :: "n"(n) : "memory")

#define LDSM_X4(r, addr) \
    asm volatile("ldmatrix.sync.aligned.m8n8.x4.shared.b16 {%0,%1,%2,%3}, [%4];" \
        : "=r"((r)[0]), "=r"((r)[1]), "=r"((r)[2]), "=r"((r)[3]) : "r"(addr))

__device__ __forceinline__ void mma16816(float* d, const uint32_t* a,
                                         uint32_t b0, uint32_t b1) {
    asm volatile(
        "mma.sync.aligned.m16n8k16.row.col.f32.f16.f16.f32 "
        "{%0,%1,%2,%3}, {%4,%5,%6,%7}, {%8,%9}, {%0,%1,%2,%3};"
        : "+f"(d[0]), "+f"(d[1]), "+f"(d[2]), "+f"(d[3])
        : "r"(a[0]), "r"(a[1]), "r"(a[2]), "r"(a[3]), "r"(b0), "r"(b1));
}

// ---------------------------------------------------------------------------
// Small kernels
// ---------------------------------------------------------------------------
__global__ void probe_mask_kernel(const unsigned int* __restrict__ w) {
    __shared__ int s_other, s_f1, s_i1;
    if (threadIdx.x == 0) { s_other = 0; s_f1 = 0; s_i1 = 0; }
    __syncthreads();
    int lo = 0, lf = 0, li = 0;
    for (int i = threadIdx.x; i < 65536; i += blockDim.x) {
        unsigned v = w[i];
        if (v == 0u) continue;
        else if (v == 1u) li++;
        else if (v == 0x3F800000u) lf++;
        else lo++;
    }
    atomicAdd(&s_other, lo); atomicAdd(&s_f1, lf); atomicAdd(&s_i1, li);
    __syncthreads();
    if (threadIdx.x == 0) {
        int mode;
        if (s_other > 1024) mode = 0;
        else if (s_f1 >= s_i1) mode = 2;
        else mode = 1;
        g_mask_mode = mode;
    }
}

// Fused: noisy = where(mask,0,likes) -> fp16 padded  AND  column partial sums
// of likes (for popular). One pass over likes. grid (ceil(KPAD/256), 16).
__global__ void premask_popular_kernel(const float* __restrict__ likes,
                                       const void* __restrict__ mask,
                                       __half* __restrict__ noisy,
                                       float* __restrict__ part) {
    const int mode = g_mask_mode;
    const int col = blockIdx.x * 256 + threadIdx.x;
    if (col >= KPAD) return;
    const int r0 = blockIdx.y * 128;

    if (col >= NITEMS) {  // padding region: zero noisy, no popular
        const __half hz = __float2half_rn(0.f);
        for (int r = 0; r < 128; r++)
            noisy[(size_t)(r0 + r) * KPAD + col] = hz;
        return;
    }

    const unsigned char* m8 = (const unsigned char*)mask;
    const int*           mi = (const int*)mask;
    const float*         mf = (const float*)mask;

    float sum = 0.f;
    #pragma unroll 4
    for (int r = 0; r < 128; r++) {
        size_t e = (size_t)(r0 + r) * NITEMS + col;
        float v = likes[e];
        sum += v;
        bool drop;
        if (mode == 0)      drop = (m8[e] != 0);
        else if (mode == 1) drop = (mi[e] != 0);
        else                drop = (mf[e] != 0.f);
        noisy[(size_t)(r0 + r) * KPAD + col] = __float2half_rn(drop ? 0.f : v);
    }
    part[blockIdx.y * NITEMS + col] = sum;
}

__global__ void popular_reduce_kernel(const float* __restrict__ part,
                                      float* __restrict__ out_pop) {
    int i = blockIdx.x * 256 + threadIdx.x;
    if (i >= NITEMS) return;
    float s = 0.f;
    #pragma unroll
    for (int c = 0; c < 16; c++) s += part[c * NITEMS + i];
    out_pop[i] = s * (1.0f / (float)BATCH);
}

// per-row l2 normalize; emit fp16 normalized AND fp16 copy of E
__global__ void norm_half_kernel(const float* __restrict__ E,
                                 __half* __restrict__ Nrmh,
                                 __half* __restrict__ Eh) {
    int row = blockIdx.x;
    int t = threadIdx.x;   // 128 threads, EMB=512 -> one float4 each
    float4 v = reinterpret_cast<const float4*>(E + (size_t)row * EMB)[t];
    float ss = v.x * v.x + v.y * v.y + v.z * v.z + v.w * v.w;
    #pragma unroll
    for (int o = 16; o > 0; o >>= 1)
        ss += __shfl_xor_sync(0xFFFFFFFFu, ss, o);
    __shared__ float ws[4];
    if ((t & 31) == 0) ws[t >> 5] = ss;
    __syncthreads();
    float tot = ws[0] + ws[1] + ws[2] + ws[3];
    float inv = rsqrtf(fmaxf(tot, 1e-12f));
    __half2* eh = reinterpret_cast<__half2*>(Eh + (size_t)row * EMB + t * 4);
    eh[0] = __floats2half2_rn(v.x, v.y);
    eh[1] = __floats2half2_rn(v.z, v.w);
    __half2* nh = reinterpret_cast<__half2*>(Nrmh + (size_t)row * EMB + t * 4);
    nh[0] = __floats2half2_rn(v.x * inv, v.y * inv);
    nh[1] = __floats2half2_rn(v.z * inv, v.w * inv);
}

// transpose + convert: in f32 [R][C] -> out fp16 [C][Rp], zero for r >= R
__global__ void transpose_half_kernel(const float* __restrict__ in,
                                      __half* __restrict__ out,
                                      int R, int C, int Rp) {
    __shared__ float t[32][33];
    int c0 = blockIdx.x * 32, r0 = blockIdx.y * 32;
    int x = threadIdx.x, y = threadIdx.y;
    #pragma unroll
    for (int i = 0; i < 32; i += 8) {
        int r = r0 + y + i, c = c0 + x;
        t[y + i][x] = (r < R && c < C) ? in[(size_t)r * C + c] : 0.f;
    }
    __syncthreads();
    #pragma unroll
    for (int i = 0; i < 32; i += 8) {
        int cc = c0 + y + i, rr = r0 + x;
        if (cc < C && rr < Rp)
            out[(size_t)cc * Rp + rr] = __float2half_rn(t[x][y + i]);
    }
}

// ---------------------------------------------------------------------------
// fp16 tensor-core GEMM: C[M,N] = act(A[M,K] @ Bt[N,K]^T + bias)
//   A: fp16 [M][lda] K-major;  Bt: fp16 [N][ldb] K-major.
//   CTA tile 128x128, BK=64, 3-stage cp.async (96KB smem), 2 CTAs/SM,
//   8 warps (2m x 4n, 64x32 each), mma.sync.m16n8k16 + ldmatrix.
// ---------------------------------------------------------------------------
enum { ACT_RELU = 0, ACT_SIG = 1, ACT_NEG = 2 };
#define BK 64
#define NSTAGE 3
#define ASZ 16384                 // 128 rows * 128B
#define SSZ 32768                 // A + B per stage

template<int ACT, bool HAS_BIAS, bool OUT_HALF>
__global__ __launch_bounds__(256, 2)
void hmma_gemm(const __half* __restrict__ A, const __half* __restrict__ Bt,
               const float* __restrict__ bias, void* __restrict__ Cout,
               int M, int N, int K, int lda, int ldb) {
    extern __shared__ __align__(128) char smem[];
    const uint32_t sbase = smem_u32(smem);

    const int tid = threadIdx.x;
    const int lane = tid & 31, wid = tid >> 5;
    const int wm = (wid & 1) * 64;        // warp m offset in tile
    const int wn = (wid >> 1) * 32;       // warp n offset in tile
    const int m0 = blockIdx.x * 128;
    const int n0 = blockIdx.y * 128;
    const int nch = K / BK;

    float acc[4][4][4];
    #pragma unroll
    for (int i = 0; i < 4; i++)
        #pragma unroll
        for (int j = 0; j < 4; j++)
            #pragma unroll
            for (int q = 0; q < 4; q++) acc[i][j][q] = 0.f;

    // ---- stage loader ----
    auto load_stage = [&](int ch, int st) {
        const int k0 = ch * BK;
        const uint32_t sA = sbase + st * SSZ;
        const uint32_t sB = sA + ASZ;
        #pragma unroll
        for (int u = 0; u < 4; u++) {
            int idx = tid + u * 256;
            int r = idx >> 3, c = idx & 7;
            const __half* src = A + (size_t)(m0 + r) * lda + k0 + c * 8;
            cp16(sA + r * 128 + ((c ^ (r & 7)) << 4), src, 16);
        }
        #pragma unroll
        for (int u = 0; u < 4; u++) {
            int idx = tid + u * 256;
            int r = idx >> 3, c = idx & 7;
            int n = n0 + r;
            const __half* src = Bt + (size_t)n * ldb + k0 + c * 8;
            cp16(sB + r * 128 + ((c ^ (r & 7)) << 4), src, (n < N) ? 16 : 0);
        }
        CP_COMMIT();
    };

    // ldmatrix lane addressing (swizzle bits constant per lane)
    const int aRow = wm + (lane & 15);
    const int aKsel = lane >> 4;            // 0/1 -> +16B within 32B k16
    const int bRow = wn + ((lane >> 4) << 3) + (lane & 7);
    const int bKsel = (lane >> 3) & 1;
    const int swz = lane & 7;

    load_stage(0, 0);
    load_stage(1, 1);

    for (int i = 0; i < nch; i++) {
        const int j = i + NSTAGE - 1;
        if (j < nch) load_stage(j, j % NSTAGE);
        else         CP_COMMIT();           // empty group keeps wait count aligned
        CP_WAIT(NSTAGE - 1);
        __syncthreads();

        const uint32_t sA = sbase + (i % NSTAGE) * SSZ;
        const uint32_t sB = sA + ASZ;
        #pragma unroll
        for (int kk = 0; kk < 4; kk++) {
            uint32_t a[4][4], b[2][4];
            const uint32_t aByte = ((2 * kk + aKsel) ^ swz) << 4;
            const uint32_t bByte = ((2 * kk + bKsel) ^ swz) << 4;
            #pragma unroll
            for (int mf = 0; mf < 4; mf++)
                LDSM_X4(a[mf], sA + (aRow + 16 * mf) * 128 + aByte);
            #pragma unroll
            for (int nf2 = 0; nf2 < 2; nf2++)
                LDSM_X4(b[nf2], sB + (bRow + 16 * nf2) * 128 + bByte);
            #pragma unroll
            for (int mf = 0; mf < 4; mf++)
                #pragma unroll
                for (int nf = 0; nf < 4; nf++)
                    mma16816(acc[mf][nf], a[mf],
                             b[nf >> 1][(nf & 1) * 2],
                             b[nf >> 1][(nf & 1) * 2 + 1]);
        }
        __syncthreads();
    }

    // ---- epilogue ----
    #pragma unroll
    for (int mf = 0; mf < 4; mf++) {
        const int row = m0 + wm + mf * 16 + (lane >> 2);
        #pragma unroll
        for (int nf = 0; nf < 4; nf++) {
            const int col = n0 + wn + nf * 8 + 2 * (lane & 3);
            if (col >= N) continue;
            float2 lo = make_float2(acc[mf][nf][0], acc[mf][nf][1]);
            float2 hi = make_float2(acc[mf][nf][2], acc[mf][nf][3]);
            if (HAS_BIAS) {
                float2 bb = *reinterpret_cast<const float2*>(bias + col);
                lo.x += bb.x; lo.y += bb.y;
                hi.x += bb.x; hi.y += bb.y;
            }
            if (ACT == ACT_RELU) {
                lo.x = fmaxf(lo.x, 0.f); lo.y = fmaxf(lo.y, 0.f);
                hi.x = fmaxf(hi.x, 0.f); hi.y = fmaxf(hi.y, 0.f);
            } else if (ACT == ACT_SIG) {
                lo.x = 1.f / (1.f + __expf(-lo.x));
                lo.y = 1.f / (1.f + __expf(-lo.y));
                hi.x = 1.f / (1.f + __expf(-hi.x));
                hi.y = 1.f / (1.f + __expf(-hi.y));
            } else {
                lo.x = -lo.x; lo.y = -lo.y;
                hi.x = -hi.x; hi.y = -hi.y;
            }
            if (OUT_HALF) {
                __half* C = (__half*)Cout;
                *reinterpret_cast<__half2*>(C + (size_t)row * N + col) =
                    __floats2half2_rn(lo.x, lo.y);
                *reinterpret_cast<__half2*>(C + (size_t)(row + 8) * N + col) =
                    __floats2half2_rn(hi.x, hi.y);
            } else {
                float* C = (float*)Cout;
                *reinterpret_cast<float2*>(C + (size_t)row * N + col) = lo;
                *reinterpret_cast<float2*>(C + (size_t)(row + 8) * N + col) = hi;
            }
        }
    }
}

// ---------------------------------------------------------------------------
// Launch
// ---------------------------------------------------------------------------
extern "C" void kernel_launch(void* const* d_in, const int* in_sizes, int n_in,
                              void* d_out, int out_size) {
    const float* likes  = (const float*)d_in[1];
    const void*  nmask  = d_in[2];
    const float* enc_w1 = (const float*)d_in[3];
    const float* enc_b1 = (const float*)d_in[4];
    const float* enc_w2 = (const float*)d_in[5];
    const float* enc_b2 = (const float*)d_in[6];
    const float* lk_w1  = (const float*)d_in[7];
    const float* lk_b1  = (const float*)d_in[8];
    const float* lk_w2  = (const float*)d_in[9];
    const float* lk_b2  = (const float*)d_in[10];
    const float* rc_w1  = (const float*)d_in[11];
    const float* rc_b1  = (const float*)d_in[12];
    const float* rc_w2  = (const float*)d_in[13];
    const float* rc_b2  = (const float*)d_in[14];

    float* out       = (float*)d_out;
    float* out_likes = out;
    float* out_sim   = out_likes + (size_t)BATCH * NITEMS;
    float* out_rec   = out_sim + (size_t)BATCH * BATCH;
    float* out_pop   = out_rec + (size_t)BATCH * NITEMS;

    __half *noisyh, *W1h, *W2h, *W3h, *W4h, *W5h, *W6h, *Hh, *Eh, *Nrmh;
    float *E, *part;
    cudaGetSymbolAddress((void**)&noisyh, g_noisyh);
    cudaGetSymbolAddress((void**)&W1h, g_W1h);
    cudaGetSymbolAddress((void**)&W2h, g_W2h);
    cudaGetSymbolAddress((void**)&W3h, g_W3h);
    cudaGetSymbolAddress((void**)&W4h, g_W4h);
    cudaGetSymbolAddress((void**)&W5h, g_W5h);
    cudaGetSymbolAddress((void**)&W6h, g_W6h);
    cudaGetSymbolAddress((void**)&Hh, g_Hh);
    cudaGetSymbolAddress((void**)&E, g_E);
    cudaGetSymbolAddress((void**)&Eh, g_Eh);
    cudaGetSymbolAddress((void**)&Nrmh, g_Nrmh);
    cudaGetSymbolAddress((void**)&part, g_part);

    const int smem = NSTAGE * SSZ;  // 96KB
    cudaFuncSetAttribute(hmma_gemm<ACT_RELU, true, true>,
                         cudaFuncAttributeMaxDynamicSharedMemorySize, smem);
    cudaFuncSetAttribute(hmma_gemm<ACT_RELU, true, false>,
                         cudaFuncAttributeMaxDynamicSharedMemorySize, smem);
    cudaFuncSetAttribute(hmma_gemm<ACT_SIG, true, false>,
                         cudaFuncAttributeMaxDynamicSharedMemorySize, smem);
    cudaFuncSetAttribute(hmma_gemm<ACT_NEG, false, false>,
                         cudaFuncAttributeMaxDynamicSharedMemorySize, smem);

    // mask probe, fused denoise+popular partial, popular reduce
    probe_mask_kernel<<<1, 256>>>((const unsigned int*)nmask);
    premask_popular_kernel<<<dim3((KPAD + 255) / 256, 16), 256>>>(
        likes, nmask, noisyh, part);
    popular_reduce_kernel<<<(NITEMS + 255) / 256, 256>>>(part, out_pop);

    // weight transposes -> fp16 K-major
    dim3 tb(32, 8);
    transpose_half_kernel<<<dim3(HID / 32, KPAD / 32), tb>>>(
        enc_w1, W1h, NITEMS, HID, KPAD);
    transpose_half_kernel<<<dim3(EMB / 32, HID / 32), tb>>>(
        enc_w2, W2h, HID, EMB, HID);
    transpose_half_kernel<<<dim3(HID / 32, EMB / 32), tb>>>(
        lk_w1, W3h, EMB, HID, EMB);
    transpose_half_kernel<<<dim3((NITEMS + 31) / 32, HID / 32), tb>>>(
        lk_w2, W4h, HID, NITEMS, HID);
    transpose_half_kernel<<<dim3(HID / 32, EMB / 32), tb>>>(
        rc_w1, W5h, EMB, HID, EMB);
    transpose_half_kernel<<<dim3((NITEMS + 31) / 32, HID / 32), tb>>>(
        rc_w2, W6h, HID, NITEMS, HID);

    // encoder
    hmma_gemm<ACT_RELU, true, true><<<dim3(BATCH / 128, HID / 128), 256, smem>>>(
        noisyh, W1h, enc_b1, Hh, BATCH, HID, KPAD, KPAD, KPAD);
    hmma_gemm<ACT_RELU, true, false><<<dim3(BATCH / 128, EMB / 128), 256, smem>>>(
        Hh, W2h, enc_b2, E, BATCH, EMB, HID, HID, HID);
    norm_half_kernel<<<BATCH, 128>>>(E, Nrmh, Eh);

    // user_sim = -(Nrm @ Nrm^T)
    hmma_gemm<ACT_NEG, false, false><<<dim3(BATCH / 128, BATCH / 128), 256, smem>>>(
        Nrmh, Nrmh, nullptr, out_sim, BATCH, BATCH, EMB, EMB, EMB);

    // likes head
    hmma_gemm<ACT_RELU, true, true><<<dim3(BATCH / 128, HID / 128), 256, smem>>>(
        Eh, W3h, lk_b1, Hh, BATCH, HID, EMB, EMB, EMB);
    hmma_gemm<ACT_SIG, true, false>
        <<<dim3(BATCH / 128, (NITEMS + 127) / 128), 256, smem>>>(
        Hh, W4h, lk_b2, out_likes, BATCH, NITEMS, HID, HID, HID);

    // rec head
    hmma_gemm<ACT_RELU, true, true><<<dim3(BATCH / 128, HID / 128), 256, smem>>>(
        Eh, W5h, rc_b1, Hh, BATCH, HID, EMB, EMB, EMB);
    hmma_gemm<ACT_SIG, true, false>
        <<<dim3(BATCH / 128, (NITEMS + 127) / 128), 256, smem>>>(
        Hh, W6h, rc_b2, out_rec, BATCH, NITEMS, HID, HID, HID);
}